// round 1
// baseline (speedup 1.0000x reference)
#include <cuda_runtime.h>
#include <math.h>

typedef unsigned long long ull;

#define Nn 4096
#define Hd 64
#define Gg 32
#define NTOPK 6
#define TWO_PI_F 6.2831853071795864769f

// ---------------- scratch (device globals; no allocation allowed) ----------------
__device__ float g_q[Nn * Hd];                 // silu(q) * 0.125 (rope applied later)
__device__ float g_k[Nn * Hd];                 // silu(k)
__device__ float g_v[Nn * Hd];
__device__ float g_KV[Gg * NTOPK * Hd * Hd];   // per (graph, m) 64x64
__device__ float g_kvec[Gg * NTOPK * 3];
__device__ int   g_start[Gg + 1];

// ---------------- f32x2 packed helpers (Blackwell FFMA2) ----------------
__device__ __forceinline__ ull pack2(float x, float y) {
    ull r; asm("mov.b64 %0, {%1, %2};" : "=l"(r) : "f"(x), "f"(y)); return r;
}
__device__ __forceinline__ ull dup2(float x) {
    ull r; asm("mov.b64 %0, {%1, %1};" : "=l"(r) : "f"(x)); return r;
}
__device__ __forceinline__ void unpack2(ull a, float& x, float& y) {
    asm("mov.b64 {%0, %1}, %2;" : "=f"(x), "=f"(y) : "l"(a));
}
__device__ __forceinline__ void fma2(ull& d, ull a, ull b) {
    asm("fma.rn.f32x2 %0, %1, %2, %0;" : "+l"(d) : "l"(a), "l"(b));
}

// =====================================================================
// Kernel 1: per-graph k-grid top-6 selection + graph node offsets.
// 1 block, 1024 threads. Warp w handles graph w (32 lanes scan 342 candidates).
// =====================================================================
__global__ __launch_bounds__(1024) void k_setup(const float* __restrict__ cell,
                                                const int* __restrict__ batch) {
    int t = threadIdx.x;
    int w = t >> 5, lane = t & 31;

    if (w < Gg) {
        float ix = 1.0f / cell[w * 9 + 0];
        float iy = 1.0f / cell[w * 9 + 4];
        float iz = 1.0f / cell[w * 9 + 8];
        const float k2max = (TWO_PI_F / 10.0f) * (TWO_PI_F / 10.0f);

        ull prev = 0;  // strictly-increasing (ksq,idx) key of last selected
        for (int s = 0; s < NTOPK; s++) {
            ull best = ~0ULL;
            int idx = 0;
            for (int a = -3; a <= 3; a++)
                for (int b = -3; b <= 3; b++)
                    for (int c = -3; c <= 3; c++) {
                        if (a == 0 && b == 0 && c == 0) continue;
                        if ((idx & 31) == lane) {
                            float kx = (TWO_PI_F * (float)a) * ix;
                            float ky = (TWO_PI_F * (float)b) * iy;
                            float kz = (TWO_PI_F * (float)c) * iz;
                            float ksq = kx * kx + ky * ky + kz * kz;
                            float eff = (ksq <= k2max) ? ksq : 1e10f;
                            ull key = (((ull)__float_as_uint(eff)) << 32) | (unsigned)idx;
                            if (key > prev && key < best) best = key;
                        }
                        idx++;
                    }
            // warp min-reduce of lexicographic key
            for (int off = 16; off; off >>= 1) {
                ull o = __shfl_xor_sync(0xffffffffu, best, off);
                if (o < best) best = o;
            }
            best = __shfl_sync(0xffffffffu, best, 0);
            prev = best;
            if (lane == 0) {
                int bi = (int)(best & 0xffffffffULL);
                int L = bi + (bi >= 171 ? 1 : 0);  // re-insert the removed (0,0,0) slot
                int a = L / 49 - 3;
                int b = (L / 7) % 7 - 3;
                int c = L % 7 - 3;
                g_kvec[(w * NTOPK + s) * 3 + 0] = (TWO_PI_F * (float)a) * ix;
                g_kvec[(w * NTOPK + s) * 3 + 1] = (TWO_PI_F * (float)b) * iy;
                g_kvec[(w * NTOPK + s) * 3 + 2] = (TWO_PI_F * (float)c) * iz;
            }
        }
    }

    if (t <= Gg) {  // lower_bound(batch, t)
        int lo = 0, hi = Nn;
        while (lo < hi) {
            int mid = (lo + hi) >> 1;
            if (batch[mid] < t) lo = mid + 1; else hi = mid;
        }
        g_start[t] = lo;
    }
}

// =====================================================================
// Kernel 2: QKV projection + silu. Grid: 256 CTAs = 128 node-tiles x 2 j-halves.
// CTA: 32 nodes x 96 j.  Thread tile: 2 nodes x 6 j, FFMA2 packed over j pairs.
// =====================================================================
__global__ __launch_bounds__(256) void k_qkv(const float* __restrict__ x,
                                             const float* __restrict__ W) {
    __shared__ float wt[64 * 98];  // W transposed: wt[h][j], j in [0,96)
    __shared__ float xs[64 * 34];  // x transposed: xs[h][node], node in [0,32)

    int bx = blockIdx.x;
    int nb = bx >> 1;   // node tile
    int jh = bx & 1;    // j half
    int t = threadIdx.x;

    // stage W half (96 rows of 64), transposed
    for (int s = t; s < 96 * 16; s += 256) {
        int j = s >> 4, h0 = (s & 15) * 4;
        float4 wv = *(const float4*)&W[(jh * 96 + j) * 64 + h0];
        wt[(h0 + 0) * 98 + j] = wv.x;
        wt[(h0 + 1) * 98 + j] = wv.y;
        wt[(h0 + 2) * 98 + j] = wv.z;
        wt[(h0 + 3) * 98 + j] = wv.w;
    }
    // stage x tile (32 nodes x 64), transposed
    for (int s = t; s < 512; s += 256) {
        int nl = s >> 4, h0 = (s & 15) * 4;
        float4 xv = *(const float4*)&x[(nb * 32 + nl) * 64 + h0];
        xs[(h0 + 0) * 34 + nl] = xv.x;
        xs[(h0 + 1) * 34 + nl] = xv.y;
        xs[(h0 + 2) * 34 + nl] = xv.z;
        xs[(h0 + 3) * 34 + nl] = xv.w;
    }
    __syncthreads();

    int ng = t & 15;        // node pair base: nodes ng*2, ng*2+1
    int jg = t >> 4;        // j group: j0 = jg*6
    int j0 = jg * 6;

    ull acc[3][2];
    #pragma unroll
    for (int i = 0; i < 3; i++) { acc[i][0] = 0ULL; acc[i][1] = 0ULL; }

    #pragma unroll 8
    for (int h = 0; h < 64; h++) {
        float xa = xs[h * 34 + ng * 2];
        float xb = xs[h * 34 + ng * 2 + 1];
        ull xda = dup2(xa), xdb = dup2(xb);
        ull w01 = *(ull*)&wt[h * 98 + j0];
        ull w23 = *(ull*)&wt[h * 98 + j0 + 2];
        ull w45 = *(ull*)&wt[h * 98 + j0 + 4];
        fma2(acc[0][0], w01, xda); fma2(acc[0][1], w01, xdb);
        fma2(acc[1][0], w23, xda); fma2(acc[1][1], w23, xdb);
        fma2(acc[2][0], w45, xda); fma2(acc[2][1], w45, xdb);
    }

    #pragma unroll
    for (int jp = 0; jp < 3; jp++) {
        #pragma unroll
        for (int nn = 0; nn < 2; nn++) {
            float v0, v1;
            unpack2(acc[jp][nn], v0, v1);
            int n = nb * 32 + ng * 2 + nn;
            #pragma unroll
            for (int ii = 0; ii < 2; ii++) {
                float val = ii ? v1 : v0;
                int j = jh * 96 + j0 + jp * 2 + ii;
                if (j < 128) val = val / (1.0f + expf(-val));  // silu
                if (j < 64)        g_q[n * 64 + j] = val * 0.125f;  // fold 1/sqrt(H)
                else if (j < 128)  g_k[n * 64 + (j - 64)] = val;
                else               g_v[n * 64 + (j - 128)] = val;
            }
        }
    }
}

// =====================================================================
// Kernel 3: KV accumulation. Grid: 192 CTAs = (g, m).
// KV[g,m][h][e] = sum_{n in g} rope_m(k[n])[h] * v[n][e]
// Thread tile: 4h x 4e in registers; nodes staged 16 at a time in smem.
// =====================================================================
__global__ __launch_bounds__(256) void k_kv(const float* __restrict__ pos) {
    int g = blockIdx.x / NTOPK, m = blockIdx.x % NTOPK;
    int n0 = g_start[g], n1 = g_start[g + 1];

    __shared__ float kr_s[16 * 64];
    __shared__ float vs[16 * 64];
    __shared__ float cs_s[16 * 2];

    int t = threadIdx.x;
    int eg = t & 15;    // e base = eg*4
    int hg = t >> 4;    // h base = hg*4

    float kvx = g_kvec[(g * NTOPK + m) * 3 + 0];
    float kvy = g_kvec[(g * NTOPK + m) * 3 + 1];
    float kvz = g_kvec[(g * NTOPK + m) * 3 + 2];

    ull acc[4][2];
    #pragma unroll
    for (int i = 0; i < 4; i++) { acc[i][0] = 0ULL; acc[i][1] = 0ULL; }

    for (int base = n0; base < n1; base += 16) {
        int cnt = min(16, n1 - base);
        __syncthreads();  // protect smem reuse from previous chunk
        if (t < cnt) {
            int n = base + t;
            float ph = pos[n * 3 + 0] * kvx + pos[n * 3 + 1] * kvy + pos[n * 3 + 2] * kvz;
            float sn, cn;
            sincosf(ph, &sn, &cn);
            cs_s[t * 2 + 0] = cn;
            cs_s[t * 2 + 1] = sn;
        }
        for (int s = t; s < cnt * 64; s += 256)
            vs[s] = g_v[base * 64 + s];
        __syncthreads();
        for (int s = t; s < cnt * 64; s += 256) {
            int nn = s >> 6, h = s & 63;
            float cn = cs_s[nn * 2 + 0], sn = cs_s[nn * 2 + 1];
            float k1 = g_k[(base + nn) * 64 + (h & 31)];
            float k2 = g_k[(base + nn) * 64 + (h & 31) + 32];
            kr_s[s] = (h < 32) ? (k1 * cn - k2 * sn) : (k1 * sn + k2 * cn);
        }
        __syncthreads();
        for (int nn = 0; nn < cnt; nn++) {
            ull ka = *(ull*)&kr_s[nn * 64 + hg * 4];
            ull kb = *(ull*)&kr_s[nn * 64 + hg * 4 + 2];
            float k0, k1, k2, k3;
            unpack2(ka, k0, k1);
            unpack2(kb, k2, k3);
            ull kd0 = dup2(k0), kd1 = dup2(k1), kd2 = dup2(k2), kd3 = dup2(k3);
            ull v01 = *(ull*)&vs[nn * 64 + eg * 4];
            ull v23 = *(ull*)&vs[nn * 64 + eg * 4 + 2];
            fma2(acc[0][0], kd0, v01); fma2(acc[0][1], kd0, v23);
            fma2(acc[1][0], kd1, v01); fma2(acc[1][1], kd1, v23);
            fma2(acc[2][0], kd2, v01); fma2(acc[2][1], kd2, v23);
            fma2(acc[3][0], kd3, v01); fma2(acc[3][1], kd3, v23);
        }
    }

    float* dst = g_KV + (size_t)(g * NTOPK + m) * 4096;
    #pragma unroll
    for (int hh = 0; hh < 4; hh++) {
        *(ull*)&dst[(hg * 4 + hh) * 64 + eg * 4]     = acc[hh][0];
        *(ull*)&dst[(hg * 4 + hh) * 64 + eg * 4 + 2] = acc[hh][1];
    }
}

// =====================================================================
// Kernel 4: update. Grid: 192 CTAs = (g, m).
// out[n][e] += sum_h rope_m(q[n])[h] * KV[g,m][h][e]   (q already scaled)
// Thread: e = t&63, hq = t>>6 owns 16 h with KV cached in 16 registers.
// 4-way partial reduce via smem, then atomicAdd (6 m contributions).
// =====================================================================
__global__ __launch_bounds__(256) void k_upd(const float* __restrict__ pos,
                                             float* __restrict__ out) {
    int g = blockIdx.x / NTOPK, m = blockIdx.x % NTOPK;
    int n0 = g_start[g], n1 = g_start[g + 1];

    __shared__ float qr_s[16 * 64];
    __shared__ float red_s[16 * 4 * 64];
    __shared__ float cs_s[16 * 2];

    int t = threadIdx.x;
    int e = t & 63;
    int hq = t >> 6;   // h base = hq*16

    const float* kvp = g_KV + (size_t)(g * NTOPK + m) * 4096;
    ull kv2[8];
    #pragma unroll
    for (int j = 0; j < 8; j++) {
        float a = kvp[(hq * 16 + 2 * j) * 64 + e];
        float b = kvp[(hq * 16 + 2 * j + 1) * 64 + e];
        kv2[j] = pack2(a, b);
    }

    float kvx = g_kvec[(g * NTOPK + m) * 3 + 0];
    float kvy = g_kvec[(g * NTOPK + m) * 3 + 1];
    float kvz = g_kvec[(g * NTOPK + m) * 3 + 2];

    for (int base = n0; base < n1; base += 16) {
        int cnt = min(16, n1 - base);
        __syncthreads();  // protect smem reuse
        if (t < cnt) {
            int n = base + t;
            float ph = pos[n * 3 + 0] * kvx + pos[n * 3 + 1] * kvy + pos[n * 3 + 2] * kvz;
            float sn, cn;
            sincosf(ph, &sn, &cn);
            cs_s[t * 2 + 0] = cn;
            cs_s[t * 2 + 1] = sn;
        }
        __syncthreads();
        for (int s = t; s < cnt * 64; s += 256) {
            int nn = s >> 6, h = s & 63;
            float cn = cs_s[nn * 2 + 0], sn = cs_s[nn * 2 + 1];
            float q1 = g_q[(base + nn) * 64 + (h & 31)];
            float q2 = g_q[(base + nn) * 64 + (h & 31) + 32];
            qr_s[s] = (h < 32) ? (q1 * cn - q2 * sn) : (q1 * sn + q2 * cn);
        }
        __syncthreads();
        for (int nn = 0; nn < cnt; nn++) {
            ull a0 = 0ULL, a1 = 0ULL;  // two chains to hide FFMA2 latency
            #pragma unroll
            for (int j = 0; j < 8; j += 2) {
                ull q2a = *(ull*)&qr_s[nn * 64 + hq * 16 + 2 * j];
                ull q2b = *(ull*)&qr_s[nn * 64 + hq * 16 + 2 * j + 2];
                fma2(a0, q2a, kv2[j]);
                fma2(a1, q2b, kv2[j + 1]);
            }
            float l0, h0, l1, h1;
            unpack2(a0, l0, h0);
            unpack2(a1, l1, h1);
            red_s[(nn * 4 + hq) * 64 + e] = (l0 + h0) + (l1 + h1);
        }
        __syncthreads();
        for (int s = t; s < cnt * 64; s += 256) {
            int nn = s >> 6, ee = s & 63;
            float sum = red_s[(nn * 4 + 0) * 64 + ee] + red_s[(nn * 4 + 1) * 64 + ee]
                      + red_s[(nn * 4 + 2) * 64 + ee] + red_s[(nn * 4 + 3) * 64 + ee];
            atomicAdd(&out[(base + nn) * 64 + ee], sum);
        }
    }
}

// =====================================================================
extern "C" void kernel_launch(void* const* d_in, const int* in_sizes, int n_in,
                              void* d_out, int out_size) {
    const float* node_feat = (const float*)d_in[0];
    const float* positions = (const float*)d_in[1];
    const float* cell      = (const float*)d_in[2];
    const int*   batch     = (const int*)d_in[3];
    const float* W_qkv     = (const float*)d_in[4];
    float* out = (float*)d_out;

    k_setup<<<1, 1024>>>(cell, batch);
    k_qkv<<<256, 256>>>(node_feat, W_qkv);
    cudaMemsetAsync(out, 0, (size_t)out_size * sizeof(float));
    k_kv<<<Gg * NTOPK, 256>>>(positions);
    k_upd<<<Gg * NTOPK, 256>>>(positions, out);
}

// round 2
// speedup vs baseline: 3.0193x; 3.0193x over previous
#include <cuda_runtime.h>
#include <math.h>

typedef unsigned long long ull;

#define Nn 4096
#define Hd 64
#define Gg 32
#define NTOPK 6
#define TWO_PI_F 6.2831853071795864769f

#define MAXC16 320   // max 16-node chunks (<= 256+32)
#define MAXC32 192   // max 32-node chunks (<= 128+32)

// ---------------- scratch (device globals; no allocation allowed) ----------------
__device__ float g_q[Nn * Hd];                 // silu(q) * 0.125
__device__ float g_k[Nn * Hd];                 // silu(k)
__device__ float g_v[Nn * Hd];
__device__ float g_KV[Gg * NTOPK * Hd * Hd];   // per (graph, m) 64x64, atomically accumulated
__device__ float g_kvec[Gg * NTOPK * 3];
__device__ int   g_start[Gg + 1];
__device__ int   g_list16[MAXC16];             // packed: start | g<<13 | cnt<<18
__device__ int   g_list32[MAXC32];
__device__ int   g_n16;
__device__ int   g_n32;

// ---------------- f32x2 packed helpers (Blackwell FFMA2) ----------------
__device__ __forceinline__ ull dup2(float x) {
    ull r; asm("mov.b64 %0, {%1, %1};" : "=l"(r) : "f"(x)); return r;
}
__device__ __forceinline__ void unpack2(ull a, float& x, float& y) {
    asm("mov.b64 {%0, %1}, %2;" : "=f"(x), "=f"(y) : "l"(a));
}
__device__ __forceinline__ void fma2(ull& d, ull a, ull b) {
    asm("fma.rn.f32x2 %0, %1, %2, %0;" : "+l"(d) : "l"(a), "l"(b));
}

// =====================================================================
// Kernel 1: per-graph k-grid top-6 (precompute keys once, 6 warp-reduces),
// graph node offsets, and chunk work-lists.
// =====================================================================
__global__ __launch_bounds__(1024) void k_setup(const float* __restrict__ cell,
                                                const int* __restrict__ batch) {
    int t = threadIdx.x;
    int w = t >> 5, lane = t & 31;

    if (t <= Gg) {  // lower_bound(batch, t)
        int lo = 0, hi = Nn;
        while (lo < hi) {
            int mid = (lo + hi) >> 1;
            if (batch[mid] < t) lo = mid + 1; else hi = mid;
        }
        g_start[t] = lo;
    }

    if (w < Gg) {
        float ix = 1.0f / cell[w * 9 + 0];
        float iy = 1.0f / cell[w * 9 + 4];
        float iz = 1.0f / cell[w * 9 + 8];
        const float k2max = (TWO_PI_F / 10.0f) * (TWO_PI_F / 10.0f);

        // precompute this lane's candidate keys ONCE (<= 11 of 342)
        ull keys[11];
        int nk = 0;
        for (int idx = lane; idx < 342; idx += 32) {
            int L = idx + (idx >= 171 ? 1 : 0);   // skip (0,0,0) slot
            int a = L / 49 - 3;
            int b = (L / 7) % 7 - 3;
            int c = L % 7 - 3;
            float kx = (TWO_PI_F * (float)a) * ix;
            float ky = (TWO_PI_F * (float)b) * iy;
            float kz = (TWO_PI_F * (float)c) * iz;
            float ksq = kx * kx + ky * ky + kz * kz;
            float eff = (ksq <= k2max) ? ksq : 1e10f;
            keys[nk++] = (((ull)__float_as_uint(eff)) << 32) | (unsigned)idx;
        }

        ull prev = 0;
        for (int s = 0; s < NTOPK; s++) {
            ull best = ~0ULL;
            #pragma unroll
            for (int i = 0; i < 11; i++)
                if (i < nk) {
                    ull kk = keys[i];
                    if (kk > prev && kk < best) best = kk;
                }
            for (int off = 16; off; off >>= 1) {
                ull o = __shfl_xor_sync(0xffffffffu, best, off);
                if (o < best) best = o;
            }
            best = __shfl_sync(0xffffffffu, best, 0);
            prev = best;
            if (lane == 0) {
                int bi = (int)(best & 0xffffffffULL);
                int L = bi + (bi >= 171 ? 1 : 0);
                int a = L / 49 - 3;
                int b = (L / 7) % 7 - 3;
                int c = L % 7 - 3;
                g_kvec[(w * NTOPK + s) * 3 + 0] = (TWO_PI_F * (float)a) * ix;
                g_kvec[(w * NTOPK + s) * 3 + 1] = (TWO_PI_F * (float)b) * iy;
                g_kvec[(w * NTOPK + s) * 3 + 2] = (TWO_PI_F * (float)c) * iz;
            }
        }
    }

    __syncthreads();
    if (t == 0) {  // build per-graph chunk lists (serial; ~300 iters)
        int i16 = 0, i32 = 0;
        for (int g = 0; g < Gg; g++) {
            int n0 = g_start[g], n1 = g_start[g + 1];
            for (int s = n0; s < n1; s += 16)
                g_list16[i16++] = s | (g << 13) | (min(16, n1 - s) << 18);
            for (int s = n0; s < n1; s += 32)
                g_list32[i32++] = s | (g << 13) | (min(32, n1 - s) << 18);
        }
        g_n16 = i16;
        g_n32 = i32;
    }
}

// =====================================================================
// Kernel 2: QKV projection + silu. 256 CTAs = 128 node-tiles x 2 j-halves.
// =====================================================================
__global__ __launch_bounds__(256) void k_qkv(const float* __restrict__ x,
                                             const float* __restrict__ W) {
    __shared__ float wt[64 * 98];
    __shared__ float xs[64 * 34];

    int bx = blockIdx.x;
    int nb = bx >> 1;
    int jh = bx & 1;
    int t = threadIdx.x;

    for (int s = t; s < 96 * 16; s += 256) {
        int j = s >> 4, h0 = (s & 15) * 4;
        float4 wv = *(const float4*)&W[(jh * 96 + j) * 64 + h0];
        wt[(h0 + 0) * 98 + j] = wv.x;
        wt[(h0 + 1) * 98 + j] = wv.y;
        wt[(h0 + 2) * 98 + j] = wv.z;
        wt[(h0 + 3) * 98 + j] = wv.w;
    }
    for (int s = t; s < 512; s += 256) {
        int nl = s >> 4, h0 = (s & 15) * 4;
        float4 xv = *(const float4*)&x[(nb * 32 + nl) * 64 + h0];
        xs[(h0 + 0) * 34 + nl] = xv.x;
        xs[(h0 + 1) * 34 + nl] = xv.y;
        xs[(h0 + 2) * 34 + nl] = xv.z;
        xs[(h0 + 3) * 34 + nl] = xv.w;
    }
    __syncthreads();

    int ng = t & 15;
    int jg = t >> 4;
    int j0 = jg * 6;

    ull acc[3][2];
    #pragma unroll
    for (int i = 0; i < 3; i++) { acc[i][0] = 0ULL; acc[i][1] = 0ULL; }

    #pragma unroll 8
    for (int h = 0; h < 64; h++) {
        float xa = xs[h * 34 + ng * 2];
        float xb = xs[h * 34 + ng * 2 + 1];
        ull xda = dup2(xa), xdb = dup2(xb);
        ull w01 = *(ull*)&wt[h * 98 + j0];
        ull w23 = *(ull*)&wt[h * 98 + j0 + 2];
        ull w45 = *(ull*)&wt[h * 98 + j0 + 4];
        fma2(acc[0][0], w01, xda); fma2(acc[0][1], w01, xdb);
        fma2(acc[1][0], w23, xda); fma2(acc[1][1], w23, xdb);
        fma2(acc[2][0], w45, xda); fma2(acc[2][1], w45, xdb);
    }

    #pragma unroll
    for (int jp = 0; jp < 3; jp++) {
        #pragma unroll
        for (int nn = 0; nn < 2; nn++) {
            float v0, v1;
            unpack2(acc[jp][nn], v0, v1);
            int n = nb * 32 + ng * 2 + nn;
            #pragma unroll
            for (int ii = 0; ii < 2; ii++) {
                float val = ii ? v1 : v0;
                int j = jh * 96 + j0 + jp * 2 + ii;
                if (j < 128) val = val / (1.0f + expf(-val));  // silu
                if (j < 64)        g_q[n * 64 + j] = val * 0.125f;
                else if (j < 128)  g_k[n * 64 + (j - 64)] = val;
                else               g_v[n * 64 + (j - 128)] = val;
            }
        }
    }
}

// =====================================================================
// Kernel 3: KV accumulation. Grid = MAXC32 * 6 CTAs; CTA = (chunk32, m).
// KV[g,m] += rope_m(K_chunk)^T @ V_chunk  via atomicAdd.
// =====================================================================
__global__ __launch_bounds__(256) void k_kv(const float* __restrict__ pos) {
    int chunk = blockIdx.x / NTOPK;
    int m = blockIdx.x % NTOPK;
    if (chunk >= g_n32) return;
    int meta = g_list32[chunk];
    int base = meta & 0x1FFF;
    int g = (meta >> 13) & 31;
    int cnt = meta >> 18;

    __shared__ float kr_s[32 * 64];
    __shared__ float vs[32 * 64];
    __shared__ float cs_s[32 * 2];

    int t = threadIdx.x;
    int eg = t & 15;    // e base = eg*4
    int hg = t >> 4;    // h base = hg*4

    float kvx = g_kvec[(g * NTOPK + m) * 3 + 0];
    float kvy = g_kvec[(g * NTOPK + m) * 3 + 1];
    float kvz = g_kvec[(g * NTOPK + m) * 3 + 2];

    if (t < cnt) {
        int n = base + t;
        float ph = pos[n * 3 + 0] * kvx + pos[n * 3 + 1] * kvy + pos[n * 3 + 2] * kvz;
        float sn, cn;
        sincosf(ph, &sn, &cn);
        cs_s[t * 2 + 0] = cn;
        cs_s[t * 2 + 1] = sn;
    }
    for (int s = t; s < cnt * 64; s += 256)
        vs[s] = g_v[base * 64 + s];
    __syncthreads();
    for (int s = t; s < cnt * 64; s += 256) {
        int nn = s >> 6, h = s & 63;
        float cn = cs_s[nn * 2 + 0], sn = cs_s[nn * 2 + 1];
        float k1 = g_k[(base + nn) * 64 + (h & 31)];
        float k2 = g_k[(base + nn) * 64 + (h & 31) + 32];
        kr_s[s] = (h < 32) ? (k1 * cn - k2 * sn) : (k1 * sn + k2 * cn);
    }
    __syncthreads();

    ull acc[4][2];
    #pragma unroll
    for (int i = 0; i < 4; i++) { acc[i][0] = 0ULL; acc[i][1] = 0ULL; }

    for (int nn = 0; nn < cnt; nn++) {
        ull ka = *(ull*)&kr_s[nn * 64 + hg * 4];
        ull kb = *(ull*)&kr_s[nn * 64 + hg * 4 + 2];
        float k0, k1, k2, k3;
        unpack2(ka, k0, k1);
        unpack2(kb, k2, k3);
        ull kd0 = dup2(k0), kd1 = dup2(k1), kd2 = dup2(k2), kd3 = dup2(k3);
        ull v01 = *(ull*)&vs[nn * 64 + eg * 4];
        ull v23 = *(ull*)&vs[nn * 64 + eg * 4 + 2];
        fma2(acc[0][0], kd0, v01); fma2(acc[0][1], kd0, v23);
        fma2(acc[1][0], kd1, v01); fma2(acc[1][1], kd1, v23);
        fma2(acc[2][0], kd2, v01); fma2(acc[2][1], kd2, v23);
        fma2(acc[3][0], kd3, v01); fma2(acc[3][1], kd3, v23);
    }

    float* dst = g_KV + (size_t)(g * NTOPK + m) * 4096;
    #pragma unroll
    for (int hh = 0; hh < 4; hh++) {
        float a0, a1, a2, a3;
        unpack2(acc[hh][0], a0, a1);
        unpack2(acc[hh][1], a2, a3);
        float* p = &dst[(hg * 4 + hh) * 64 + eg * 4];
        atomicAdd(p + 0, a0);
        atomicAdd(p + 1, a1);
        atomicAdd(p + 2, a2);
        atomicAdd(p + 3, a3);
    }
}

// =====================================================================
// Kernel 4: update. Grid = MAXC16 CTAs; CTA = chunk16, loops m inside,
// accumulates across m in registers, stores final result (no atomics).
// Thread: eg = t&31 (e-pair 2*eg), ng = t>>5 (nodes 2ng, 2ng+1).
// =====================================================================
__global__ __launch_bounds__(256) void k_upd(const float* __restrict__ pos,
                                             float* __restrict__ out) {
    int b = blockIdx.x;
    if (b >= g_n16) return;
    int meta = g_list16[b];
    int base = meta & 0x1FFF;
    int g = (meta >> 13) & 31;
    int cnt = meta >> 18;

    __shared__ float qr_s[16 * 64];
    __shared__ float cs_s[16 * 2];

    int t = threadIdx.x;
    int eg = t & 31;    // e pair: e = 2*eg
    int ng = t >> 5;    // nodes 2*ng, 2*ng+1

    ull acc0 = 0ULL, acc1 = 0ULL;

    for (int m = 0; m < NTOPK; m++) {
        float kvx = g_kvec[(g * NTOPK + m) * 3 + 0];
        float kvy = g_kvec[(g * NTOPK + m) * 3 + 1];
        float kvz = g_kvec[(g * NTOPK + m) * 3 + 2];

        __syncthreads();  // protect smem reuse from previous m
        if (t < 16) {
            int n = min(base + t, Nn - 1);
            float ph = pos[n * 3 + 0] * kvx + pos[n * 3 + 1] * kvy + pos[n * 3 + 2] * kvz;
            float sn, cn;
            sincosf(ph, &sn, &cn);
            cs_s[t * 2 + 0] = cn;
            cs_s[t * 2 + 1] = sn;
        }
        __syncthreads();
        for (int s = t; s < 16 * 64; s += 256) {
            int nn = s >> 6, h = s & 63;
            int n = min(base + nn, Nn - 1);
            float cn = cs_s[nn * 2 + 0], sn = cs_s[nn * 2 + 1];
            float q1 = g_q[n * 64 + (h & 31)];
            float q2 = g_q[n * 64 + (h & 31) + 32];
            qr_s[s] = (h < 32) ? (q1 * cn - q2 * sn) : (q1 * sn + q2 * cn);
        }
        __syncthreads();

        const float* kv = g_KV + (size_t)(g * NTOPK + m) * 4096;
        #pragma unroll 8
        for (int h = 0; h < 64; h++) {
            ull kvv = *(const ull*)&kv[h * 64 + eg * 2];
            float qa = qr_s[(2 * ng) * 64 + h];
            float qb = qr_s[(2 * ng + 1) * 64 + h];
            fma2(acc0, dup2(qa), kvv);
            fma2(acc1, dup2(qb), kvv);
        }
    }

    int n0 = base + 2 * ng;
    if (2 * ng < cnt)     *(ull*)&out[n0 * 64 + eg * 2] = acc0;
    if (2 * ng + 1 < cnt) *(ull*)&out[(n0 + 1) * 64 + eg * 2] = acc1;
}

// =====================================================================
extern "C" void kernel_launch(void* const* d_in, const int* in_sizes, int n_in,
                              void* d_out, int out_size) {
    const float* node_feat = (const float*)d_in[0];
    const float* positions = (const float*)d_in[1];
    const float* cell      = (const float*)d_in[2];
    const int*   batch     = (const int*)d_in[3];
    const float* W_qkv     = (const float*)d_in[4];
    float* out = (float*)d_out;

    void* kv_ptr = nullptr;
    cudaGetSymbolAddress(&kv_ptr, g_KV);

    k_setup<<<1, 1024>>>(cell, batch);
    k_qkv<<<256, 256>>>(node_feat, W_qkv);
    cudaMemsetAsync(kv_ptr, 0, sizeof(float) * Gg * NTOPK * Hd * Hd);
    k_kv<<<MAXC32 * NTOPK, 256>>>(positions);
    k_upd<<<MAXC16, 256>>>(positions, out);
    (void)out_size; (void)n_in; (void)in_sizes;
}

// round 3
// speedup vs baseline: 3.1129x; 1.0310x over previous
#include <cuda_runtime.h>
#include <math.h>

typedef unsigned long long ull;

#define Nn 4096
#define Hd 64
#define Gg 32
#define NTOPK 6
#define TWO_PI_F 6.2831853071795864769f

#define MAXC16 320   // max 16-node chunks
#define MAXC32 192   // max 32-node chunks

// ---------------- scratch ----------------
__device__ float g_q[Nn * Hd];                 // silu(q) * 0.125
__device__ float g_k[Nn * Hd];                 // silu(k)
__device__ float g_v[Nn * Hd];
__device__ float g_KV[Gg * NTOPK * Hd * Hd];   // per (graph, m) 64x64, red-accumulated
__device__ float g_kvec[Gg * NTOPK * 3];
__device__ int   g_start[Gg + 1];
__device__ int   g_list16[MAXC16];             // start | g<<13 | cnt<<18
__device__ int   g_list32[MAXC32];
__device__ int   g_n16;
__device__ int   g_n32;

// ---------------- f32x2 packed helpers ----------------
__device__ __forceinline__ ull dup2(float x) {
    ull r; asm("mov.b64 %0, {%1, %1};" : "=l"(r) : "f"(x)); return r;
}
__device__ __forceinline__ void unpack2(ull a, float& x, float& y) {
    asm("mov.b64 {%0, %1}, %2;" : "=f"(x), "=f"(y) : "l"(a));
}
__device__ __forceinline__ void fma2(ull& d, ull a, ull b) {
    asm("fma.rn.f32x2 %0, %1, %2, %0;" : "+l"(d) : "l"(a), "l"(b));
}
__device__ __forceinline__ void red2(float* p, float a, float b) {
    asm volatile("red.global.add.v2.f32 [%0], {%1, %2};" :: "l"(p), "f"(a), "f"(b) : "memory");
}

// =====================================================================
// Kernel 1: k-grid top-6 per graph, node offsets, chunk lists.
// =====================================================================
__global__ __launch_bounds__(1024) void k_setup(const float* __restrict__ cell,
                                                const int* __restrict__ batch) {
    int t = threadIdx.x;
    int w = t >> 5, lane = t & 31;

    if (t <= Gg) {
        int lo = 0, hi = Nn;
        while (lo < hi) {
            int mid = (lo + hi) >> 1;
            if (batch[mid] < t) lo = mid + 1; else hi = mid;
        }
        g_start[t] = lo;
    }

    if (w < Gg) {
        float ix = 1.0f / cell[w * 9 + 0];
        float iy = 1.0f / cell[w * 9 + 4];
        float iz = 1.0f / cell[w * 9 + 8];
        const float k2max = (TWO_PI_F / 10.0f) * (TWO_PI_F / 10.0f);

        ull keys[11];
        int nk = 0;
        for (int idx = lane; idx < 342; idx += 32) {
            int L = idx + (idx >= 171 ? 1 : 0);
            int a = L / 49 - 3;
            int b = (L / 7) % 7 - 3;
            int c = L % 7 - 3;
            float kx = (TWO_PI_F * (float)a) * ix;
            float ky = (TWO_PI_F * (float)b) * iy;
            float kz = (TWO_PI_F * (float)c) * iz;
            float ksq = kx * kx + ky * ky + kz * kz;
            float eff = (ksq <= k2max) ? ksq : 1e10f;
            keys[nk++] = (((ull)__float_as_uint(eff)) << 32) | (unsigned)idx;
        }

        ull prev = 0;
        for (int s = 0; s < NTOPK; s++) {
            ull best = ~0ULL;
            #pragma unroll
            for (int i = 0; i < 11; i++)
                if (i < nk) {
                    ull kk = keys[i];
                    if (kk > prev && kk < best) best = kk;
                }
            for (int off = 16; off; off >>= 1) {
                ull o = __shfl_xor_sync(0xffffffffu, best, off);
                if (o < best) best = o;
            }
            best = __shfl_sync(0xffffffffu, best, 0);
            prev = best;
            if (lane == 0) {
                int bi = (int)(best & 0xffffffffULL);
                int L = bi + (bi >= 171 ? 1 : 0);
                int a = L / 49 - 3;
                int b = (L / 7) % 7 - 3;
                int c = L % 7 - 3;
                g_kvec[(w * NTOPK + s) * 3 + 0] = (TWO_PI_F * (float)a) * ix;
                g_kvec[(w * NTOPK + s) * 3 + 1] = (TWO_PI_F * (float)b) * iy;
                g_kvec[(w * NTOPK + s) * 3 + 2] = (TWO_PI_F * (float)c) * iz;
            }
        }
    }

    __syncthreads();
    if (t == 0) {
        int i16 = 0, i32 = 0;
        for (int g = 0; g < Gg; g++) {
            int n0 = g_start[g], n1 = g_start[g + 1];
            for (int s = n0; s < n1; s += 16)
                g_list16[i16++] = s | (g << 13) | (min(16, n1 - s) << 18);
            for (int s = n0; s < n1; s += 32)
                g_list32[i32++] = s | (g << 13) | (min(32, n1 - s) << 18);
        }
        g_n16 = i16;
        g_n32 = i32;
    }
}

// =====================================================================
// Kernel 2: QKV projection + silu.
// =====================================================================
__global__ __launch_bounds__(256) void k_qkv(const float* __restrict__ x,
                                             const float* __restrict__ W) {
    __shared__ float wt[64 * 98];
    __shared__ float xs[64 * 34];

    int bx = blockIdx.x;
    int nb = bx >> 1;
    int jh = bx & 1;
    int t = threadIdx.x;

    for (int s = t; s < 96 * 16; s += 256) {
        int j = s >> 4, h0 = (s & 15) * 4;
        float4 wv = *(const float4*)&W[(jh * 96 + j) * 64 + h0];
        wt[(h0 + 0) * 98 + j] = wv.x;
        wt[(h0 + 1) * 98 + j] = wv.y;
        wt[(h0 + 2) * 98 + j] = wv.z;
        wt[(h0 + 3) * 98 + j] = wv.w;
    }
    for (int s = t; s < 512; s += 256) {
        int nl = s >> 4, h0 = (s & 15) * 4;
        float4 xv = *(const float4*)&x[(nb * 32 + nl) * 64 + h0];
        xs[(h0 + 0) * 34 + nl] = xv.x;
        xs[(h0 + 1) * 34 + nl] = xv.y;
        xs[(h0 + 2) * 34 + nl] = xv.z;
        xs[(h0 + 3) * 34 + nl] = xv.w;
    }
    __syncthreads();

    int ng = t & 15;
    int jg = t >> 4;
    int j0 = jg * 6;

    ull acc[3][2];
    #pragma unroll
    for (int i = 0; i < 3; i++) { acc[i][0] = 0ULL; acc[i][1] = 0ULL; }

    #pragma unroll 8
    for (int h = 0; h < 64; h++) {
        float xa = xs[h * 34 + ng * 2];
        float xb = xs[h * 34 + ng * 2 + 1];
        ull xda = dup2(xa), xdb = dup2(xb);
        ull w01 = *(ull*)&wt[h * 98 + j0];
        ull w23 = *(ull*)&wt[h * 98 + j0 + 2];
        ull w45 = *(ull*)&wt[h * 98 + j0 + 4];
        fma2(acc[0][0], w01, xda); fma2(acc[0][1], w01, xdb);
        fma2(acc[1][0], w23, xda); fma2(acc[1][1], w23, xdb);
        fma2(acc[2][0], w45, xda); fma2(acc[2][1], w45, xdb);
    }

    #pragma unroll
    for (int jp = 0; jp < 3; jp++) {
        #pragma unroll
        for (int nn = 0; nn < 2; nn++) {
            float v0, v1;
            unpack2(acc[jp][nn], v0, v1);
            int n = nb * 32 + ng * 2 + nn;
            #pragma unroll
            for (int ii = 0; ii < 2; ii++) {
                float val = ii ? v1 : v0;
                int j = jh * 96 + j0 + jp * 2 + ii;
                if (j < 128) val = val / (1.0f + expf(-val));
                if (j < 64)        g_q[n * 64 + j] = val * 0.125f;
                else if (j < 128)  g_k[n * 64 + (j - 64)] = val;
                else               g_v[n * 64 + (j - 128)] = val;
            }
        }
    }
}

// =====================================================================
// Kernel 3: KV accumulation. CTA = (chunk32, m). Duplicated rope'd k in
// smem (no MOV dups in inner loop); red.v2 epilogue.
// =====================================================================
__global__ __launch_bounds__(256) void k_kv(const float* __restrict__ pos) {
    int chunk = blockIdx.x / NTOPK;
    int m = blockIdx.x % NTOPK;
    if (chunk >= g_n32) return;
    int meta = g_list32[chunk];
    int base = meta & 0x1FFF;
    int g = (meta >> 13) & 31;
    int cnt = meta >> 18;

    __shared__ ull   krd[32 * 64];      // 16KB, {kr,kr} pairs
    __shared__ float vs[32 * 64];       // 8KB
    __shared__ float2 cs_s[32];

    int t = threadIdx.x;
    int eg = t & 15;    // e base = eg*4
    int hg = t >> 4;    // h base = hg*4

    float kvx = g_kvec[(g * NTOPK + m) * 3 + 0];
    float kvy = g_kvec[(g * NTOPK + m) * 3 + 1];
    float kvz = g_kvec[(g * NTOPK + m) * 3 + 2];

    if (t < cnt) {
        int n = base + t;
        float ph = pos[n * 3 + 0] * kvx + pos[n * 3 + 1] * kvy + pos[n * 3 + 2] * kvz;
        float sn, cn;
        sincosf(ph, &sn, &cn);
        cs_s[t] = make_float2(cn, sn);
    }
    for (int s = t; s < cnt * 16; s += 256)
        *(float4*)&vs[s * 4] = *(const float4*)&g_v[base * 64 + s * 4];
    __syncthreads();
    for (int s = t; s < cnt * 64; s += 256) {
        int nn = s >> 6, h = s & 63;
        float2 cc = cs_s[nn];
        float k1 = g_k[(base + nn) * 64 + (h & 31)];
        float k2 = g_k[(base + nn) * 64 + (h & 31) + 32];
        float kr = (h < 32) ? (k1 * cc.x - k2 * cc.y) : (k1 * cc.y + k2 * cc.x);
        krd[s] = dup2(kr);
    }
    __syncthreads();

    ull acc[4][2];
    #pragma unroll
    for (int i = 0; i < 4; i++) { acc[i][0] = 0ULL; acc[i][1] = 0ULL; }

    #pragma unroll 4
    for (int nn = 0; nn < cnt; nn++) {
        ulonglong2 ka = *(const ulonglong2*)&krd[nn * 64 + hg * 4];
        ulonglong2 kb = *(const ulonglong2*)&krd[nn * 64 + hg * 4 + 2];
        ulonglong2 vv = *(const ulonglong2*)&vs[nn * 64 + eg * 4];
        fma2(acc[0][0], ka.x, vv.x); fma2(acc[0][1], ka.x, vv.y);
        fma2(acc[1][0], ka.y, vv.x); fma2(acc[1][1], ka.y, vv.y);
        fma2(acc[2][0], kb.x, vv.x); fma2(acc[2][1], kb.x, vv.y);
        fma2(acc[3][0], kb.y, vv.x); fma2(acc[3][1], kb.y, vv.y);
    }

    float* dst = g_KV + (size_t)(g * NTOPK + m) * 4096;
    #pragma unroll
    for (int hh = 0; hh < 4; hh++) {
        float a0, a1, a2, a3;
        unpack2(acc[hh][0], a0, a1);
        unpack2(acc[hh][1], a2, a3);
        float* p = &dst[(hg * 4 + hh) * 64 + eg * 4];
        red2(p, a0, a1);
        red2(p + 2, a2, a3);
    }
}

// =====================================================================
// Kernel 4: update. CTA = chunk16. All 6 m rope'd q precomputed in smem
// (duplicated f32x2), 2 rounds of 3 m; accs across all m; single store.
// Thread: nn = t>>4 (node), eq = t&15 (e-quad).
// =====================================================================
__global__ __launch_bounds__(256) void k_upd(const float* __restrict__ pos,
                                             float* __restrict__ out) {
    int b = blockIdx.x;
    if (b >= g_n16) return;
    int meta = g_list16[b];
    int base = meta & 0x1FFF;
    int g = (meta >> 13) & 31;
    int cnt = meta >> 18;

    __shared__ ull    qd_s[3 * 16 * 64];  // 24KB: [mr][node][h] dup'd
    __shared__ float  qtile[16 * 64];     // 4KB
    __shared__ float2 cs_s[3 * 16];

    int t = threadIdx.x;
    int nn = t >> 4;
    int eq = t & 15;

    // stage q tile (16 nodes x 64) via float4
    {
        int node = t >> 4, h0 = (t & 15) * 4;
        int n = min(base + node, Nn - 1);
        *(float4*)&qtile[node * 64 + h0] = *(const float4*)&g_q[n * 64 + h0];
    }
    __syncthreads();

    ull acc0 = 0ULL, acc1 = 0ULL;

    #pragma unroll
    for (int r = 0; r < 2; r++) {
        if (r) __syncthreads();   // protect qd_s reuse
        if (t < 48) {
            int mr = t >> 4, node = t & 15;
            int m = r * 3 + mr;
            float kvx = g_kvec[(g * NTOPK + m) * 3 + 0];
            float kvy = g_kvec[(g * NTOPK + m) * 3 + 1];
            float kvz = g_kvec[(g * NTOPK + m) * 3 + 2];
            int n = min(base + node, Nn - 1);
            float ph = pos[n * 3 + 0] * kvx + pos[n * 3 + 1] * kvy + pos[n * 3 + 2] * kvz;
            float sn, cn;
            sincosf(ph, &sn, &cn);
            cs_s[t] = make_float2(cn, sn);
        }
        __syncthreads();
        for (int s = t; s < 3 * 16 * 64; s += 256) {
            int mr = s >> 10;
            int node = (s >> 6) & 15;
            int h = s & 63;
            float2 cc = cs_s[mr * 16 + node];
            float q1 = qtile[node * 64 + (h & 31)];
            float q2 = qtile[node * 64 + (h & 31) + 32];
            float qr = (h < 32) ? (q1 * cc.x - q2 * cc.y) : (q1 * cc.y + q2 * cc.x);
            qd_s[s] = dup2(qr);
        }
        __syncthreads();

        #pragma unroll
        for (int mr = 0; mr < 3; mr++) {
            const ull* kv = (const ull*)(g_KV + (size_t)(g * NTOPK + r * 3 + mr) * 4096);
            const ull* qrow = &qd_s[(mr * 16 + nn) * 64];
            #pragma unroll 8
            for (int h = 0; h < 64; h++) {
                ull qd = qrow[h];
                ulonglong2 kvv = *(const ulonglong2*)&kv[h * 32 + eq * 2];
                fma2(acc0, qd, kvv.x);
                fma2(acc1, qd, kvv.y);
            }
        }
    }

    if (nn < cnt) {
        ulonglong2 res;
        res.x = acc0;
        res.y = acc1;
        *(ulonglong2*)&out[(base + nn) * 64 + eq * 4] = res;
    }
}

// =====================================================================
extern "C" void kernel_launch(void* const* d_in, const int* in_sizes, int n_in,
                              void* d_out, int out_size) {
    const float* node_feat = (const float*)d_in[0];
    const float* positions = (const float*)d_in[1];
    const float* cell      = (const float*)d_in[2];
    const int*   batch     = (const int*)d_in[3];
    const float* W_qkv     = (const float*)d_in[4];
    float* out = (float*)d_out;

    void* kv_ptr = nullptr;
    cudaGetSymbolAddress(&kv_ptr, g_KV);

    cudaMemsetAsync(kv_ptr, 0, sizeof(float) * Gg * NTOPK * Hd * Hd);
    k_setup<<<1, 1024>>>(cell, batch);
    k_qkv<<<256, 256>>>(node_feat, W_qkv);
    k_kv<<<MAXC32 * NTOPK, 256>>>(positions);
    k_upd<<<MAXC16, 256>>>(positions, out);
    (void)out_size; (void)n_in; (void)in_sizes;
}

// round 4
// speedup vs baseline: 4.0807x; 1.3109x over previous
#include <cuda_runtime.h>
#include <math.h>

typedef unsigned long long ull;

#define Nn 4096
#define Hd 64
#define Gg 32
#define NTOPK 6
#define TWO_PI_F 6.2831853071795864769f

#define MAXC16 320
#define MAXC32 192

// ---------------- scratch ----------------
__device__ float g_q[Nn * Hd];                 // silu(q) * 0.125
__device__ float g_k[Nn * Hd];                 // silu(k)
__device__ float g_v[Nn * Hd];
__device__ float g_KV[Gg * NTOPK * Hd * Hd];   // per (graph, m) 64x64
__device__ float g_kvec[Gg * NTOPK * 3];
__device__ int   g_start[Gg + 1];
__device__ int   g_list16[MAXC16];             // start | g<<13 | cnt<<18
__device__ int   g_list32[MAXC32];
__device__ int   g_n16;
__device__ int   g_n32;

// ---------------- f32x2 helpers ----------------
__device__ __forceinline__ ull dup2(float x) {
    ull r; asm("mov.b64 %0, {%1, %1};" : "=l"(r) : "f"(x)); return r;
}
__device__ __forceinline__ void unpack2(ull a, float& x, float& y) {
    asm("mov.b64 {%0, %1}, %2;" : "=f"(x), "=f"(y) : "l"(a));
}
__device__ __forceinline__ void fma2(ull& d, ull a, ull b) {
    asm("fma.rn.f32x2 %0, %1, %2, %0;" : "+l"(d) : "l"(a), "l"(b));
}
__device__ __forceinline__ void red2(float* p, float a, float b) {
    asm volatile("red.global.add.v2.f32 [%0], {%1, %2};" :: "l"(p), "f"(a), "f"(b) : "memory");
}

// =====================================================================
// Kernel 1: k-grid top-6 per graph, node offsets, chunk lists.
// =====================================================================
__global__ __launch_bounds__(1024) void k_setup(const float* __restrict__ cell,
                                                const int* __restrict__ batch) {
    int t = threadIdx.x;
    int w = t >> 5, lane = t & 31;

    if (t <= Gg) {
        int lo = 0, hi = Nn;
        while (lo < hi) {
            int mid = (lo + hi) >> 1;
            if (batch[mid] < t) lo = mid + 1; else hi = mid;
        }
        g_start[t] = lo;
    }

    if (w < Gg) {
        float ix = 1.0f / cell[w * 9 + 0];
        float iy = 1.0f / cell[w * 9 + 4];
        float iz = 1.0f / cell[w * 9 + 8];
        const float k2max = (TWO_PI_F / 10.0f) * (TWO_PI_F / 10.0f);

        ull keys[11];
        int nk = 0;
        for (int idx = lane; idx < 342; idx += 32) {
            int L = idx + (idx >= 171 ? 1 : 0);
            int a = L / 49 - 3;
            int b = (L / 7) % 7 - 3;
            int c = L % 7 - 3;
            float kx = (TWO_PI_F * (float)a) * ix;
            float ky = (TWO_PI_F * (float)b) * iy;
            float kz = (TWO_PI_F * (float)c) * iz;
            float ksq = kx * kx + ky * ky + kz * kz;
            float eff = (ksq <= k2max) ? ksq : 1e10f;
            keys[nk++] = (((ull)__float_as_uint(eff)) << 32) | (unsigned)idx;
        }

        ull prev = 0;
        for (int s = 0; s < NTOPK; s++) {
            ull best = ~0ULL;
            #pragma unroll
            for (int i = 0; i < 11; i++)
                if (i < nk) {
                    ull kk = keys[i];
                    if (kk > prev && kk < best) best = kk;
                }
            for (int off = 16; off; off >>= 1) {
                ull o = __shfl_xor_sync(0xffffffffu, best, off);
                if (o < best) best = o;
            }
            best = __shfl_sync(0xffffffffu, best, 0);
            prev = best;
            if (lane == 0) {
                int bi = (int)(best & 0xffffffffULL);
                int L = bi + (bi >= 171 ? 1 : 0);
                int a = L / 49 - 3;
                int b = (L / 7) % 7 - 3;
                int c = L % 7 - 3;
                g_kvec[(w * NTOPK + s) * 3 + 0] = (TWO_PI_F * (float)a) * ix;
                g_kvec[(w * NTOPK + s) * 3 + 1] = (TWO_PI_F * (float)b) * iy;
                g_kvec[(w * NTOPK + s) * 3 + 2] = (TWO_PI_F * (float)c) * iz;
            }
        }
    }

    __syncthreads();
    if (t == 0) {
        int i16 = 0, i32 = 0;
        for (int g = 0; g < Gg; g++) {
            int n0 = g_start[g], n1 = g_start[g + 1];
            for (int s = n0; s < n1; s += 16)
                g_list16[i16++] = s | (g << 13) | (min(16, n1 - s) << 18);
            for (int s = n0; s < n1; s += 32)
                g_list32[i32++] = s | (g << 13) | (min(32, n1 - s) << 18);
        }
        g_n16 = i16;
        g_n32 = i32;
    }
}

// =====================================================================
// Kernel 2: QKV projection + silu.
// =====================================================================
__global__ __launch_bounds__(256) void k_qkv(const float* __restrict__ x,
                                             const float* __restrict__ W) {
    __shared__ float wt[64 * 98];
    __shared__ float xs[64 * 34];

    int bx = blockIdx.x;
    int nb = bx >> 1;
    int jh = bx & 1;
    int t = threadIdx.x;

    for (int s = t; s < 96 * 16; s += 256) {
        int j = s >> 4, h0 = (s & 15) * 4;
        float4 wv = *(const float4*)&W[(jh * 96 + j) * 64 + h0];
        wt[(h0 + 0) * 98 + j] = wv.x;
        wt[(h0 + 1) * 98 + j] = wv.y;
        wt[(h0 + 2) * 98 + j] = wv.z;
        wt[(h0 + 3) * 98 + j] = wv.w;
    }
    for (int s = t; s < 512; s += 256) {
        int nl = s >> 4, h0 = (s & 15) * 4;
        float4 xv = *(const float4*)&x[(nb * 32 + nl) * 64 + h0];
        xs[(h0 + 0) * 34 + nl] = xv.x;
        xs[(h0 + 1) * 34 + nl] = xv.y;
        xs[(h0 + 2) * 34 + nl] = xv.z;
        xs[(h0 + 3) * 34 + nl] = xv.w;
    }
    __syncthreads();

    int ng = t & 15;
    int jg = t >> 4;
    int j0 = jg * 6;

    ull acc[3][2];
    #pragma unroll
    for (int i = 0; i < 3; i++) { acc[i][0] = 0ULL; acc[i][1] = 0ULL; }

    #pragma unroll 8
    for (int h = 0; h < 64; h++) {
        float xa = xs[h * 34 + ng * 2];
        float xb = xs[h * 34 + ng * 2 + 1];
        ull xda = dup2(xa), xdb = dup2(xb);
        ull w01 = *(ull*)&wt[h * 98 + j0];
        ull w23 = *(ull*)&wt[h * 98 + j0 + 2];
        ull w45 = *(ull*)&wt[h * 98 + j0 + 4];
        fma2(acc[0][0], w01, xda); fma2(acc[0][1], w01, xdb);
        fma2(acc[1][0], w23, xda); fma2(acc[1][1], w23, xdb);
        fma2(acc[2][0], w45, xda); fma2(acc[2][1], w45, xdb);
    }

    #pragma unroll
    for (int jp = 0; jp < 3; jp++) {
        #pragma unroll
        for (int nn = 0; nn < 2; nn++) {
            float v0, v1;
            unpack2(acc[jp][nn], v0, v1);
            int n = nb * 32 + ng * 2 + nn;
            #pragma unroll
            for (int ii = 0; ii < 2; ii++) {
                float val = ii ? v1 : v0;
                int j = jh * 96 + j0 + jp * 2 + ii;
                if (j < 128) val = val / (1.0f + expf(-val));
                if (j < 64)        g_q[n * 64 + j] = val * 0.125f;
                else if (j < 128)  g_k[n * 64 + (j - 64)] = val;
                else               g_v[n * 64 + (j - 128)] = val;
            }
        }
    }
}

// =====================================================================
// Kernel 3: KV accumulation. CTA = (chunk32, m); all-smem inner loop;
// red.v2 epilogue.
// =====================================================================
__global__ __launch_bounds__(256) void k_kv(const float* __restrict__ pos) {
    int chunk = blockIdx.x / NTOPK;
    int m = blockIdx.x % NTOPK;
    if (chunk >= g_n32) return;
    int meta = g_list32[chunk];
    int base = meta & 0x1FFF;
    int g = (meta >> 13) & 31;
    int cnt = meta >> 18;

    __shared__ ull   krd[32 * 64];
    __shared__ float vs[32 * 64];
    __shared__ float2 cs_s[32];

    int t = threadIdx.x;
    int eg = t & 15;
    int hg = t >> 4;

    float kvx = g_kvec[(g * NTOPK + m) * 3 + 0];
    float kvy = g_kvec[(g * NTOPK + m) * 3 + 1];
    float kvz = g_kvec[(g * NTOPK + m) * 3 + 2];

    if (t < cnt) {
        int n = base + t;
        float ph = pos[n * 3 + 0] * kvx + pos[n * 3 + 1] * kvy + pos[n * 3 + 2] * kvz;
        float sn, cn;
        sincosf(ph, &sn, &cn);
        cs_s[t] = make_float2(cn, sn);
    }
    for (int s = t; s < cnt * 16; s += 256)
        *(float4*)&vs[s * 4] = *(const float4*)&g_v[base * 64 + s * 4];
    __syncthreads();
    for (int s = t; s < cnt * 64; s += 256) {
        int nn = s >> 6, h = s & 63;
        float2 cc = cs_s[nn];
        float k1 = g_k[(base + nn) * 64 + (h & 31)];
        float k2 = g_k[(base + nn) * 64 + (h & 31) + 32];
        float kr = (h < 32) ? (k1 * cc.x - k2 * cc.y) : (k1 * cc.y + k2 * cc.x);
        krd[s] = dup2(kr);
    }
    __syncthreads();

    ull acc[4][2];
    #pragma unroll
    for (int i = 0; i < 4; i++) { acc[i][0] = 0ULL; acc[i][1] = 0ULL; }

    #pragma unroll 4
    for (int nn = 0; nn < cnt; nn++) {
        ulonglong2 ka = *(const ulonglong2*)&krd[nn * 64 + hg * 4];
        ulonglong2 kb = *(const ulonglong2*)&krd[nn * 64 + hg * 4 + 2];
        ulonglong2 vv = *(const ulonglong2*)&vs[nn * 64 + eg * 4];
        fma2(acc[0][0], ka.x, vv.x); fma2(acc[0][1], ka.x, vv.y);
        fma2(acc[1][0], ka.y, vv.x); fma2(acc[1][1], ka.y, vv.y);
        fma2(acc[2][0], kb.x, vv.x); fma2(acc[2][1], kb.x, vv.y);
        fma2(acc[3][0], kb.y, vv.x); fma2(acc[3][1], kb.y, vv.y);
    }

    float* dst = g_KV + (size_t)(g * NTOPK + m) * 4096;
    #pragma unroll
    for (int hh = 0; hh < 4; hh++) {
        float a0, a1, a2, a3;
        unpack2(acc[hh][0], a0, a1);
        unpack2(acc[hh][1], a2, a3);
        float* p = &dst[(hg * 4 + hh) * 64 + eg * 4];
        red2(p, a0, a1);
        red2(p + 2, a2, a3);
    }
}

// =====================================================================
// Kernel 4: update. CTA = chunk32. Per m: KV tile staged to smem via
// register-prefetched coalesced float4 loads; rope'd q dup'd in [h][node]
// smem. Inner loop: 2x LDS.128 + 4 FFMA2 per h. NO global loads in loop.
// Thread: np = t>>4 (nodes 2np, 2np+1), eq = t&15 (e quad).
// =====================================================================
__global__ __launch_bounds__(256) void k_upd(const float* __restrict__ pos,
                                             float* __restrict__ out) {
    int b = blockIdx.x;
    if (b >= g_n32) return;
    int meta = g_list32[b];
    int base = meta & 0x1FFF;
    int g = (meta >> 13) & 31;
    int cnt = meta >> 18;

    __shared__ float  qtile[32 * 64];     // 8KB    [node][h]
    __shared__ float2 cs_s[NTOPK * 32];   // 1.5KB
    __shared__ ull    qrd[64 * 34];       // 17.4KB [h][node] dup'd, pad 34
    __shared__ float  kvs[64 * 64];       // 16KB   [h][e]

    int t = threadIdx.x;
    int np = t >> 4;
    int eq = t & 15;

    // stage q tile (coalesced: thread -> node=t>>3, h0=(t&7)*8)
    {
        int node = t >> 3, h0 = (t & 7) * 8;
        int n = min(base + node, Nn - 1);
        *(float4*)&qtile[node * 64 + h0]     = *(const float4*)&g_q[n * 64 + h0];
        *(float4*)&qtile[node * 64 + h0 + 4] = *(const float4*)&g_q[n * 64 + h0 + 4];
    }
    // cos/sin for all m x node
    if (t < NTOPK * 32) {
        int m = t >> 5, node = t & 31;
        float kvx = g_kvec[(g * NTOPK + m) * 3 + 0];
        float kvy = g_kvec[(g * NTOPK + m) * 3 + 1];
        float kvz = g_kvec[(g * NTOPK + m) * 3 + 2];
        int n = min(base + node, Nn - 1);
        float ph = pos[n * 3 + 0] * kvx + pos[n * 3 + 1] * kvy + pos[n * 3 + 2] * kvz;
        float sn, cn;
        sincosf(ph, &sn, &cn);
        cs_s[t] = make_float2(cn, sn);
    }

    // prefetch KV for m=0 (coalesced float4)
    float4 pf[4];
    {
        const float* kv0 = g_KV + (size_t)(g * NTOPK) * 4096;
        #pragma unroll
        for (int i = 0; i < 4; i++) pf[i] = *(const float4*)&kv0[(i * 256 + t) * 4];
    }

    ull accA0 = 0ULL, accA1 = 0ULL, accB0 = 0ULL, accB1 = 0ULL;
    __syncthreads();

    for (int m = 0; m < NTOPK; m++) {
        // commit prefetched KV tile to smem
        #pragma unroll
        for (int i = 0; i < 4; i++) *(float4*)&kvs[(i * 256 + t) * 4] = pf[i];
        // rope'd q, duplicated, [h][node]
        #pragma unroll
        for (int i = 0; i < 8; i++) {
            int s = i * 256 + t;
            int h = s & 63, node = s >> 6;
            float2 cc = cs_s[m * 32 + node];
            float q1 = qtile[node * 64 + (h & 31)];
            float q2 = qtile[node * 64 + (h & 31) + 32];
            float qr = (h < 32) ? (q1 * cc.x - q2 * cc.y) : (q1 * cc.y + q2 * cc.x);
            qrd[h * 34 + node] = dup2(qr);
        }
        __syncthreads();

        // prefetch next m's KV while computing
        if (m + 1 < NTOPK) {
            const float* kvn = g_KV + (size_t)(g * NTOPK + m + 1) * 4096;
            #pragma unroll
            for (int i = 0; i < 4; i++) pf[i] = *(const float4*)&kvn[(i * 256 + t) * 4];
        }

        #pragma unroll 8
        for (int h = 0; h < 64; h++) {
            ulonglong2 qq = *(const ulonglong2*)&qrd[h * 34 + 2 * np];
            ulonglong2 kk = *(const ulonglong2*)&kvs[h * 64 + eq * 4];
            fma2(accA0, qq.x, kk.x); fma2(accA1, qq.x, kk.y);
            fma2(accB0, qq.y, kk.x); fma2(accB1, qq.y, kk.y);
        }
        __syncthreads();  // before overwriting kvs/qrd
    }

    int na = base + 2 * np;
    if (2 * np < cnt) {
        ulonglong2 r; r.x = accA0; r.y = accA1;
        *(ulonglong2*)&out[na * 64 + eq * 4] = r;
    }
    if (2 * np + 1 < cnt) {
        ulonglong2 r; r.x = accB0; r.y = accB1;
        *(ulonglong2*)&out[(na + 1) * 64 + eq * 4] = r;
    }
}

// =====================================================================
extern "C" void kernel_launch(void* const* d_in, const int* in_sizes, int n_in,
                              void* d_out, int out_size) {
    const float* node_feat = (const float*)d_in[0];
    const float* positions = (const float*)d_in[1];
    const float* cell      = (const float*)d_in[2];
    const int*   batch     = (const int*)d_in[3];
    const float* W_qkv     = (const float*)d_in[4];
    float* out = (float*)d_out;

    void* kv_ptr = nullptr;
    cudaGetSymbolAddress(&kv_ptr, g_KV);

    cudaMemsetAsync(kv_ptr, 0, sizeof(float) * Gg * NTOPK * Hd * Hd);
    k_setup<<<1, 1024>>>(cell, batch);
    k_qkv<<<256, 256>>>(node_feat, W_qkv);
    k_kv<<<MAXC32 * NTOPK, 256>>>(positions);
    k_upd<<<MAXC32, 256>>>(positions, out);
    (void)out_size; (void)n_in; (void)in_sizes;
}